// round 9
// baseline (speedup 1.0000x reference)
#include <cuda_runtime.h>
#include <cuda_fp16.h>
#include <cstdint>

#define N_NEURON 4096
#define N_BATCH  32
#define N_STEPS  300
#define NCTA     128

// ---------------- device scratch (allocation-free rule: __device__ globals) ----
__device__ __align__(256) __half g_W16[(size_t)N_NEURON * N_NEURON];
__device__ __align__(256) __half g_r16[2][N_BATCH * N_NEURON];
__device__ unsigned g_cnt;
__device__ unsigned g_gen;

// ---------------- W fp32 -> fp16 fragment pack (once per replay) --------------
// per 32-col tile: entry (jt, kb, lane) = 16 halves (32 B)
__global__ void convert_w(const float* __restrict__ W) {
    int idx = blockIdx.x * blockDim.x + threadIdx.x;
    if (idx >= 128 * 256 * 32) return;
    int lane = idx & 31;
    int kb   = (idx >> 5) & 255;
    int jt   = idx >> 13;
    int k0   = kb * 16 + (lane & 3) * 2;
    int g    = lane >> 2;
    __half h[16];
    #pragma unroll
    for (int nb = 0; nb < 4; ++nb) {
        int j = jt * 32 + nb * 8 + g;
        h[nb * 4 + 0] = __float2half(W[(size_t)(k0    ) * N_NEURON + j]);
        h[nb * 4 + 1] = __float2half(W[(size_t)(k0 + 1) * N_NEURON + j]);
        h[nb * 4 + 2] = __float2half(W[(size_t)(k0 + 8) * N_NEURON + j]);
        h[nb * 4 + 3] = __float2half(W[(size_t)(k0 + 9) * N_NEURON + j]);
    }
    uint4* dst = (uint4*)(g_W16 + (size_t)idx * 16);
    dst[0] = ((const uint4*)h)[0];
    dst[1] = ((const uint4*)h)[1];
}

// ---------------- smem layout ---------------------------------------------------
// 4 W planes: [plane][kb_local 0..95][lane] 16B  (planes: t0.lo, t0.hi, t1.lo, t1.hi)
#define SM_KB        96                      // smem-cached kb entries of the 128 local
#define PLANE        (SM_KB * 512)           // 49152
#define BUF_OFF      (4 * PLANE)             // 196608
#define SMEM_TOTAL   (BUF_OFF + 5 * 4096)    // 217088  (buf[5][32][32] f32)

__device__ __forceinline__ unsigned ld_acq(unsigned* p) {
    unsigned v;
    asm volatile("ld.acquire.gpu.global.u32 %0, [%1];" : "=r"(v) : "l"(p) : "memory");
    return v;
}
__device__ __forceinline__ void bar_arrive(int tid, unsigned target) {
    __syncthreads();
    if (tid == 0) {
        __threadfence();
        unsigned arr = atomicAdd(&g_cnt, 1);
        if (arr == NCTA - 1) {
            atomicExch(&g_cnt, 0);
            __threadfence();
            atomicExch(&g_gen, target);
        }
    }
}
__device__ __forceinline__ void bar_wait(int tid, unsigned target) {
    if (tid == 0) {
        while ((int)(ld_acq(&g_gen) - target) < 0) {}
    }
    __syncthreads();
}
__device__ __forceinline__ void lds128(uint4& d, uint32_t addr) {
    asm volatile("ld.shared.v4.u32 {%0,%1,%2,%3}, [%4];"
        : "=r"(d.x), "=r"(d.y), "=r"(d.z), "=r"(d.w) : "r"(addr));
}
__device__ __forceinline__ void stcg32(void* p, uint32_t v) {
    asm volatile("st.global.cg.u32 [%0], %1;" :: "l"(p), "r"(v) : "memory");
}
__device__ __forceinline__ uint32_t h2u(float a, float b) {
    __half2 h = __floats2half2_rn(a, b);
    return *(uint32_t*)&h;
}
__device__ __forceinline__ void mma_16816(float c[4], const uint4& a, uint32_t b0, uint32_t b1) {
    asm volatile("mma.sync.aligned.m16n8k16.row.col.f32.f16.f16.f32 "
        "{%0,%1,%2,%3}, {%4,%5,%6,%7}, {%8,%9}, {%0,%1,%2,%3};\n"
        : "+f"(c[0]), "+f"(c[1]), "+f"(c[2]), "+f"(c[3])
        : "r"(a.x), "r"(a.y), "r"(a.z), "r"(a.w), "r"(b0), "r"(b1));
}
// local kb (0..127) used by warp at iteration i (12 smem + 4 tail, pattern SSS T)
__device__ __forceinline__ int kb_of(int warp, int i) {
    int g = i >> 2, r = i & 3;
    return (r < 3) ? (warp * 12 + g * 3 + r) : (SM_KB + warp * 4 + g);
}

// ---------------- persistent fused simulation kernel ---------------------------
__global__ void __launch_bounds__(256, 1) __cluster_dims__(2, 1, 1)
persist_kernel(const float* __restrict__ ff, const float* __restrict__ rec0,
               float* __restrict__ out)
{
    extern __shared__ __align__(16) char sm[];
    float* buf = (float*)(sm + BUF_OFF);    // buf[5][32][32]; slot 4 = incoming

    const int tid  = threadIdx.x;
    const int warp = tid >> 5;
    const int lane = tid & 31;
    const int bid  = blockIdx.x;
    const int j0   = bid * 32;              // this CTA's epilogue columns
    uint32_t rank;
    asm("mov.u32 %0, %%cluster_ctarank;" : "=r"(rank));
    const uint32_t peer = rank ^ 1u;
    const int klo = (int)rank * 128;        // this CTA's k-half (in kb units)

    uint32_t smbase;
    asm("{ .reg .u64 t0; cvta.to.shared.u64 t0, %1; cvt.u32.u64 %0, t0; }"
        : "=r"(smbase) : "l"(sm));

    // W fragment tiles for the 64-column pair tile
    const uint4* __restrict__ gB0 = (const uint4*)g_W16 + (size_t)(bid & ~1) * 256 * 64;
    const uint4* __restrict__ gB1 = (const uint4*)g_W16 + (size_t)(bid |  1) * 256 * 64;

    const int bb = tid >> 3;
    const int jl = (tid & 7) * 4;
    const int j  = j0 + jl;

    const unsigned base = ld_acq(&g_gen);   // relative base: replay-safe

    // ---- prologue: cache 96 local kbs of both tiles into 4 smem planes --------
    for (int s = tid; s < SM_KB * 32; s += 256) {
        int kbl = s >> 5, ls = s & 31;
        int kba = klo + kbl;
        uint32_t d = smbase + (uint32_t)(kbl * 512 + ls * 16);
        const char* s0 = (const char*)&gB0[((size_t)kba * 32 + ls) * 2];
        const char* s1 = (const char*)&gB1[((size_t)kba * 32 + ls) * 2];
        asm volatile("cp.async.cg.shared.global [%0], [%1], 16;" :: "r"(d            ), "l"(s0     ));
        asm volatile("cp.async.cg.shared.global [%0], [%1], 16;" :: "r"(d + PLANE    ), "l"(s0 + 16));
        asm volatile("cp.async.cg.shared.global [%0], [%1], 16;" :: "r"(d + 2*PLANE  ), "l"(s1     ));
        asm volatile("cp.async.cg.shared.global [%0], [%1], 16;" :: "r"(d + 3*PLANE  ), "l"(s1 + 16));
    }
    asm volatile("cp.async.commit_group;");
    asm volatile("cp.async.wait_group 0;");

    // ---- state init in registers; publish A generation 0 ----
    float rc[4], rt[4], av[4];
    {
        const size_t idx = (size_t)bb * N_NEURON + j;
        float4 r0 = *(const float4*)&rec0[idx];
        float4 f0 = __ldg((const float4*)&ff[((size_t)bb * N_STEPS) * N_NEURON + j]);
        rc[0] = r0.x; rc[1] = r0.y; rc[2] = r0.z; rc[3] = r0.w;
        rt[0] = fmaxf(f0.x + r0.x, 0.f); rt[1] = fmaxf(f0.y + r0.y, 0.f);
        rt[2] = fmaxf(f0.z + r0.z, 0.f); rt[3] = fmaxf(f0.w + r0.w, 0.f);
        av[0] = av[1] = av[2] = av[3] = 0.f;
        int kb = j >> 4, kk = j & 15;
        int rb2 = bb >> 4, g = bb & 7;
        int reg   = ((bb >> 3) & 1) | ((kk >> 3) << 1);
        int lane0 = (g << 2) | ((kk & 7) >> 1);
        __half2* basep = (__half2*)g_r16[0];
        stcg32(&basep[((size_t)(kb * 2 + rb2) * 32 + lane0    ) * 4 + reg], h2u(rt[0], rt[1]));
        stcg32(&basep[((size_t)(kb * 2 + rb2) * 32 + lane0 + 1) * 4 + reg], h2u(rt[2], rt[3]));
    }
    bar_arrive(tid, base + 1);

    const float E_SYN  = 0.95122942450071403f;
    const float DT_SYN = 0.05f;
    const float E_TAU  = 0.90483741803595957f;
    const float DT_TAU = 0.1f;

    for (int t = 0; t < N_STEPS; ++t) {
        const int cur = t & 1, nxt = cur ^ 1;
        const uint4* __restrict__ gA = (const uint4*)g_r16[cur];

        const float4 ffv = __ldg((const float4*)&ff[((size_t)bb * N_STEPS + t) * N_NEURON + j]);

        float c[2][8][4];
        #pragma unroll
        for (int rb = 0; rb < 2; ++rb)
            #pragma unroll
            for (int nb = 0; nb < 8; ++nb)
                #pragma unroll
                for (int x = 0; x < 4; ++x) c[rb][nb][x] = 0.f;

        // ---- un-gated prefetches (overlap the barrier wait): W tail + smem B ---
        uint4 Bt[2][4];
        #pragma unroll
        for (int p = 0; p < 2; ++p) {
            int kba = klo + SM_KB + warp * 4 + p;
            Bt[p][0] = __ldg(&gB0[((size_t)kba * 32 + lane) * 2 + 0]);
            Bt[p][1] = __ldg(&gB0[((size_t)kba * 32 + lane) * 2 + 1]);
            Bt[p][2] = __ldg(&gB1[((size_t)kba * 32 + lane) * 2 + 0]);
            Bt[p][3] = __ldg(&gB1[((size_t)kba * 32 + lane) * 2 + 1]);
        }
        uint4 Bs[2][4];
        {
            uint32_t off = smbase + (uint32_t)((warp * 12) * 512 + lane * 16);
            lds128(Bs[0][0], off);
            lds128(Bs[0][1], off + PLANE);
            lds128(Bs[0][2], off + 2 * PLANE);
            lds128(Bs[0][3], off + 3 * PLANE);
        }

        // ---- wait: all CTAs published generation t ----
        bar_wait(tid, base + 1 + (unsigned)t);

        // ---- A prefetch ring (gated) ----
        uint4 Ar0[3], Ar1[3];
        #pragma unroll
        for (int p = 0; p < 3; ++p) {
            int ka = klo + kb_of(warp, p);
            Ar0[p] = __ldcg(&gA[((size_t)ka * 2 + 0) * 32 + lane]);
            Ar1[p] = __ldcg(&gA[((size_t)ka * 2 + 1) * 32 + lane]);
        }

        #pragma unroll
        for (int i = 0; i < 16; ++i) {
            const int g = i >> 2, r = i & 3;
            uint4 A0 = Ar0[i % 3], A1 = Ar1[i % 3];
            uint4 Q0, Q1, Q2, Q3;
            if (r < 3) {
                const int s = g * 3 + r;
                const int db = s & 1;
                Q0 = Bs[db][0]; Q1 = Bs[db][1]; Q2 = Bs[db][2]; Q3 = Bs[db][3];
                if (s + 1 < 12) {
                    uint32_t off = smbase + (uint32_t)((warp * 12 + s + 1) * 512 + lane * 16);
                    lds128(Bs[(s + 1) & 1][0], off);
                    lds128(Bs[(s + 1) & 1][1], off + PLANE);
                    lds128(Bs[(s + 1) & 1][2], off + 2 * PLANE);
                    lds128(Bs[(s + 1) & 1][3], off + 3 * PLANE);
                }
            } else {
                Q0 = Bt[g & 1][0]; Q1 = Bt[g & 1][1]; Q2 = Bt[g & 1][2]; Q3 = Bt[g & 1][3];
                if (g + 2 < 4) {
                    int kba = klo + SM_KB + warp * 4 + g + 2;
                    Bt[g & 1][0] = __ldg(&gB0[((size_t)kba * 32 + lane) * 2 + 0]);
                    Bt[g & 1][1] = __ldg(&gB0[((size_t)kba * 32 + lane) * 2 + 1]);
                    Bt[g & 1][2] = __ldg(&gB1[((size_t)kba * 32 + lane) * 2 + 0]);
                    Bt[g & 1][3] = __ldg(&gB1[((size_t)kba * 32 + lane) * 2 + 1]);
                }
            }

            mma_16816(c[0][0], A0, Q0.x, Q0.y);
            mma_16816(c[0][1], A0, Q0.z, Q0.w);
            mma_16816(c[0][2], A0, Q1.x, Q1.y);
            mma_16816(c[0][3], A0, Q1.z, Q1.w);
            mma_16816(c[0][4], A0, Q2.x, Q2.y);
            mma_16816(c[0][5], A0, Q2.z, Q2.w);
            mma_16816(c[0][6], A0, Q3.x, Q3.y);
            mma_16816(c[0][7], A0, Q3.z, Q3.w);
            mma_16816(c[1][0], A1, Q0.x, Q0.y);
            mma_16816(c[1][1], A1, Q0.z, Q0.w);
            mma_16816(c[1][2], A1, Q1.x, Q1.y);
            mma_16816(c[1][3], A1, Q1.z, Q1.w);
            mma_16816(c[1][4], A1, Q2.x, Q2.y);
            mma_16816(c[1][5], A1, Q2.z, Q2.w);
            mma_16816(c[1][6], A1, Q3.x, Q3.y);
            mma_16816(c[1][7], A1, Q3.z, Q3.w);

            if (i + 3 < 16) {
                int nk = klo + kb_of(warp, i + 3);
                Ar0[i % 3] = __ldcg(&gA[((size_t)nk * 2 + 0) * 32 + lane]);
                Ar1[i % 3] = __ldcg(&gA[((size_t)nk * 2 + 1) * 32 + lane]);
            }
        }

        // ---- reduction: partner half first, DSMEM send, then own half ---------
        // own cols (epilogue) = nb [rank*4, rank*4+4); partner = the other 4
        const int hb_partner = (rank == 0) ? 4 : 0;
        const int hb_own     = (rank == 0) ? 0 : 4;

        __syncthreads();
        if (warp >= 4) {
            float* b = buf + (warp - 4) * 1024;
            #pragma unroll
            for (int rb = 0; rb < 2; ++rb)
                #pragma unroll
                for (int nb = 0; nb < 4; ++nb)
                    #pragma unroll
                    for (int x = 0; x < 4; ++x) {
                        int m = rb * 16 + (lane >> 2) + ((x >= 2) ? 8 : 0);
                        int n = nb * 8 + (lane & 3) * 2 + (x & 1);
                        b[m * 32 + n] = c[rb][hb_partner + nb][x];
                    }
        }
        __syncthreads();
        if (warp < 4) {
            float* b = buf + warp * 1024;
            #pragma unroll
            for (int rb = 0; rb < 2; ++rb)
                #pragma unroll
                for (int nb = 0; nb < 4; ++nb)
                    #pragma unroll
                    for (int x = 0; x < 4; ++x) {
                        int m = rb * 16 + (lane >> 2) + ((x >= 2) ? 8 : 0);
                        int n = nb * 8 + (lane & 3) * 2 + (x & 1);
                        b[m * 32 + n] += c[rb][hb_partner + nb][x];
                    }
        }
        __syncthreads();
        // send summed partner half [32x32] into peer's buf[4]
        {
            float4 p0 = *(const float4*)&buf[0 * 1024 + bb * 32 + jl];
            float4 p1 = *(const float4*)&buf[1 * 1024 + bb * 32 + jl];
            float4 p2 = *(const float4*)&buf[2 * 1024 + bb * 32 + jl];
            float4 p3 = *(const float4*)&buf[3 * 1024 + bb * 32 + jl];
            float v0 = p0.x + p1.x + p2.x + p3.x;
            float v1 = p0.y + p1.y + p2.y + p3.y;
            float v2 = p0.z + p1.z + p2.z + p3.z;
            float v3 = p0.w + p1.w + p2.w + p3.w;
            uint32_t loc = smbase + (uint32_t)(BUF_OFF + 4 * 4096 + (bb * 32 + jl) * 4);
            uint32_t rem;
            asm("mapa.shared::cluster.u32 %0, %1, %2;" : "=r"(rem) : "r"(loc), "r"(peer));
            asm volatile("st.shared::cluster.v4.f32 [%0], {%1,%2,%3,%4};"
                :: "r"(rem), "f"(v0), "f"(v1), "f"(v2), "f"(v3) : "memory");
        }
        __syncthreads();
        // own half into the same 4 buffers
        if (warp >= 4) {
            float* b = buf + (warp - 4) * 1024;
            #pragma unroll
            for (int rb = 0; rb < 2; ++rb)
                #pragma unroll
                for (int nb = 0; nb < 4; ++nb)
                    #pragma unroll
                    for (int x = 0; x < 4; ++x) {
                        int m = rb * 16 + (lane >> 2) + ((x >= 2) ? 8 : 0);
                        int n = nb * 8 + (lane & 3) * 2 + (x & 1);
                        b[m * 32 + n] = c[rb][hb_own + nb][x];
                    }
        }
        __syncthreads();
        if (warp < 4) {
            float* b = buf + warp * 1024;
            #pragma unroll
            for (int rb = 0; rb < 2; ++rb)
                #pragma unroll
                for (int nb = 0; nb < 4; ++nb)
                    #pragma unroll
                    for (int x = 0; x < 4; ++x) {
                        int m = rb * 16 + (lane >> 2) + ((x >= 2) ? 8 : 0);
                        int n = nb * 8 + (lane & 3) * 2 + (x & 1);
                        b[m * 32 + n] += c[rb][hb_own + nb][x];
                    }
        }
        __syncthreads();
        // pairwise sync: partner's incoming (buf[4]) arrived; our send delivered
        asm volatile("barrier.cluster.arrive.aligned;" ::: "memory");
        asm volatile("barrier.cluster.wait.aligned;"   ::: "memory");

        // ---- epilogue: h = own 4 bufs + partner incoming ----
        float h[4];
        {
            float4 p0 = *(const float4*)&buf[0 * 1024 + bb * 32 + jl];
            float4 p1 = *(const float4*)&buf[1 * 1024 + bb * 32 + jl];
            float4 p2 = *(const float4*)&buf[2 * 1024 + bb * 32 + jl];
            float4 p3 = *(const float4*)&buf[3 * 1024 + bb * 32 + jl];
            float4 pi = *(const float4*)&buf[4 * 1024 + bb * 32 + jl];
            h[0] = p0.x + p1.x + p2.x + p3.x + pi.x;
            h[1] = p0.y + p1.y + p2.y + p3.y + pi.y;
            h[2] = p0.z + p1.z + p2.z + p3.z + pi.z;
            h[3] = p0.w + p1.w + p2.w + p3.w + pi.w;
        }

        const float fv[4] = {ffv.x, ffv.y, ffv.z, ffv.w};
        #pragma unroll
        for (int x = 0; x < 4; ++x) {
            rc[x] = rc[x] * E_SYN + h[x] * DT_SYN;
            float nl = fmaxf(fv[x] + rc[x], 0.0f);
            rt[x] = rt[x] * E_TAU + nl * DT_TAU;
        }

        // publish next-step A fragments; then global arrive
        {
            int kb = j >> 4, kk = j & 15;
            int rb2 = bb >> 4, g = bb & 7;
            int reg   = ((bb >> 3) & 1) | ((kk >> 3) << 1);
            int lane0 = (g << 2) | ((kk & 7) >> 1);
            __half2* basep = (__half2*)g_r16[nxt];
            stcg32(&basep[((size_t)(kb * 2 + rb2) * 32 + lane0    ) * 4 + reg], h2u(rt[0], rt[1]));
            stcg32(&basep[((size_t)(kb * 2 + rb2) * 32 + lane0 + 1) * 4 + reg], h2u(rt[2], rt[3]));
        }
        bar_arrive(tid, base + 2 + (unsigned)t);

        // window accumulation + output (off the critical path)
        if (t >= 90) {
            av[0] += rt[0]; av[1] += rt[1]; av[2] += rt[2]; av[3] += rt[3];
            if (t >= 100 && ((t - 100) % 10) == 0) {
                const int w = (t - 100) / 10;
                *(float4*)&out[((size_t)bb * 20 + w) * N_NEURON + j] =
                    make_float4(av[0] * 0.1f, av[1] * 0.1f, av[2] * 0.1f, av[3] * 0.1f);
                av[0] = av[1] = av[2] = av[3] = 0.f;
            }
        }
    }
}

// ---------------- launch ------------------------------------------------------
extern "C" void kernel_launch(void* const* d_in, const int* in_sizes, int n_in,
                              void* d_out, int out_size) {
    const float* W    = (const float*)d_in[0];   // Wab_T [4096,4096] f32
    const float* ff   = (const float*)d_in[1];   // ff_input [32,300,4096] f32
    const float* rec0 = (const float*)d_in[2];   // rec0 [32,4096] f32
    float* out = (float*)d_out;                  // [32,20,4096] f32

    cudaFuncSetAttribute(persist_kernel, cudaFuncAttributeMaxDynamicSharedMemorySize, SMEM_TOTAL);

    convert_w<<<(128 * 256 * 32 + 255) / 256, 256>>>(W);
    persist_kernel<<<NCTA, 256, SMEM_TOTAL>>>(ff, rec0, out);
}

// round 10
// speedup vs baseline: 1.2576x; 1.2576x over previous
#include <cuda_runtime.h>
#include <cuda_fp16.h>
#include <cstdint>

#define N_NEURON 4096
#define N_BATCH  32
#define N_STEPS  300
#define NCTA     128
#define NTHREAD  512

// ---------------- device scratch (allocation-free rule: __device__ globals) ----
__device__ __align__(256) __half g_W16[(size_t)N_NEURON * N_NEURON];
__device__ __align__(256) __half g_r16[2][N_BATCH * N_NEURON];
__device__ unsigned g_cnt;
__device__ unsigned g_gen;

// ---------------- W fp32 -> fp16 fragment pack (once per replay) --------------
__global__ void convert_w(const float* __restrict__ W) {
    int idx = blockIdx.x * blockDim.x + threadIdx.x;
    if (idx >= 128 * 256 * 32) return;
    int lane = idx & 31;
    int kb   = (idx >> 5) & 255;
    int jt   = idx >> 13;
    int k0   = kb * 16 + (lane & 3) * 2;
    int g    = lane >> 2;
    __half h[16];
    #pragma unroll
    for (int nb = 0; nb < 4; ++nb) {
        int j = jt * 32 + nb * 8 + g;
        h[nb * 4 + 0] = __float2half(W[(size_t)(k0    ) * N_NEURON + j]);
        h[nb * 4 + 1] = __float2half(W[(size_t)(k0 + 1) * N_NEURON + j]);
        h[nb * 4 + 2] = __float2half(W[(size_t)(k0 + 8) * N_NEURON + j]);
        h[nb * 4 + 3] = __float2half(W[(size_t)(k0 + 9) * N_NEURON + j]);
    }
    uint4* dst = (uint4*)(g_W16 + (size_t)idx * 16);
    dst[0] = ((const uint4*)h)[0];
    dst[1] = ((const uint4*)h)[1];
}

// ---------------- smem layout ---------------------------------------------------
#define WC_KB        192                      // kb entries cached in smem (of 256)
#define PLANE_BYTES  (WC_KB * 512)            // 98304 per plane
#define RED_OFF      (2 * PLANE_BYTES)        // 196608
#define RED_BYTES    (8 * 32 * 32 * 4)        // 32768 (8 buffers)
#define SMEM_TOTAL   (RED_OFF + RED_BYTES)    // 229376 = 224 KB

#define SM_KB_W      12                       // smem kbs per warp (192/16)
#define TL_KB_W      4                        // L2-tail kbs per warp (64/16)

__device__ __forceinline__ unsigned ld_acq(unsigned* p) {
    unsigned v;
    asm volatile("ld.acquire.gpu.global.u32 %0, [%1];" : "=r"(v) : "l"(p) : "memory");
    return v;
}
__device__ __forceinline__ void bar_arrive(int tid, unsigned target) {
    __syncthreads();
    if (tid == 0) {
        __threadfence();
        unsigned arr = atomicAdd(&g_cnt, 1);
        if (arr == NCTA - 1) {
            atomicExch(&g_cnt, 0);
            __threadfence();
            atomicExch(&g_gen, target);
        }
    }
}
__device__ __forceinline__ void bar_wait(int tid, unsigned target) {
    if (tid == 0) {
        while ((int)(ld_acq(&g_gen) - target) < 0) {}
    }
    __syncthreads();
}
__device__ __forceinline__ void lds128(uint4& d, uint32_t addr) {
    asm volatile("ld.shared.v4.u32 {%0,%1,%2,%3}, [%4];"
        : "=r"(d.x), "=r"(d.y), "=r"(d.z), "=r"(d.w) : "r"(addr));
}
__device__ __forceinline__ void stcg32(void* p, uint32_t v) {
    asm volatile("st.global.cg.u32 [%0], %1;" :: "l"(p), "r"(v) : "memory");
}
__device__ __forceinline__ uint32_t h2u(float a, float b) {
    __half2 h = __floats2half2_rn(a, b);
    return *(uint32_t*)&h;
}
__device__ __forceinline__ void mma_16816(float c[4], const uint4& a, uint32_t b0, uint32_t b1) {
    asm volatile("mma.sync.aligned.m16n8k16.row.col.f32.f16.f16.f32 "
        "{%0,%1,%2,%3}, {%4,%5,%6,%7}, {%8,%9}, {%0,%1,%2,%3};\n"
        : "+f"(c[0]), "+f"(c[1]), "+f"(c[2]), "+f"(c[3])
        : "r"(a.x), "r"(a.y), "r"(a.z), "r"(a.w), "r"(b0), "r"(b1));
}
// kb used by warp at iteration i of 16 (pattern: 3 smem, 1 tail per 4 iters)
__device__ __forceinline__ int kb_of(int warp, int i) {
    int g = i >> 2, r = i & 3;
    return (r < 3) ? (warp * SM_KB_W + g * 3 + r) : (WC_KB + warp * TL_KB_W + g);
}

// ---------------- persistent fused simulation kernel ---------------------------
__global__ void __launch_bounds__(NTHREAD, 1) persist_kernel(
    const float* __restrict__ ff, const float* __restrict__ rec0,
    float* __restrict__ out)
{
    extern __shared__ __align__(16) char sm[];
    float* red = (float*)(sm + RED_OFF);

    const int tid  = threadIdx.x;
    const int warp = tid >> 5;          // 0..15
    const int lane = tid & 31;
    const int jt   = blockIdx.x;
    const int j0   = jt * 32;

    uint32_t smbase;
    asm("{ .reg .u64 t0; cvta.to.shared.u64 t0, %1; cvt.u32.u64 %0, t0; }"
        : "=r"(smbase) : "l"(sm));

    const uint4* __restrict__ gB = (const uint4*)g_W16 + (size_t)jt * 256 * 64;

    // epilogue ownership: thread -> (bb, 2 consecutive j)
    const int bb = tid >> 4;            // 0..31
    const int jl = (tid & 15) * 2;      // 0..30 (even)
    const int j  = j0 + jl;

    const unsigned base = ld_acq(&g_gen);   // relative base: replay-safe

    // ---- prologue: cache 192 kb-entries of W stripe into two smem planes ------
    {
        const char* src = (const char*)gB;
        for (int s = tid; s < WC_KB * 32; s += NTHREAD) {
            uint32_t d0 = smbase + s * 16;
            uint32_t d1 = smbase + PLANE_BYTES + s * 16;
            const char* g0 = src + (size_t)s * 32;
            asm volatile("cp.async.cg.shared.global [%0], [%1], 16;" :: "r"(d0), "l"(g0));
            asm volatile("cp.async.cg.shared.global [%0], [%1], 16;" :: "r"(d1), "l"(g0 + 16));
        }
        asm volatile("cp.async.commit_group;");
        asm volatile("cp.async.wait_group 0;");
    }

    // ---- state init in registers; publish A generation 0 ----
    float rc[2], rt[2], av[2];
    {
        const size_t idx = (size_t)bb * N_NEURON + j;
        float2 r0 = *(const float2*)&rec0[idx];
        float2 f0 = __ldg((const float2*)&ff[((size_t)bb * N_STEPS) * N_NEURON + j]);
        rc[0] = r0.x; rc[1] = r0.y;
        rt[0] = fmaxf(f0.x + r0.x, 0.f); rt[1] = fmaxf(f0.y + r0.y, 0.f);
        av[0] = av[1] = 0.f;
        int kb = j >> 4, kk = j & 15;
        int rb2 = bb >> 4, g = bb & 7;
        int reg   = ((bb >> 3) & 1) | ((kk >> 3) << 1);
        int lane0 = (g << 2) | ((kk & 7) >> 1);
        __half2* basep = (__half2*)g_r16[0];
        stcg32(&basep[((size_t)(kb * 2 + rb2) * 32 + lane0) * 4 + reg], h2u(rt[0], rt[1]));
    }
    bar_arrive(tid, base + 1);

    const float E_SYN  = 0.95122942450071403f;
    const float DT_SYN = 0.05f;
    const float E_TAU  = 0.90483741803595957f;
    const float DT_TAU = 0.1f;

    for (int t = 0; t < N_STEPS; ++t) {
        const int cur = t & 1, nxt = cur ^ 1;
        const uint4* __restrict__ gA = (const uint4*)g_r16[cur];

        const float2 ffv = __ldg((const float2*)&ff[((size_t)bb * N_STEPS + t) * N_NEURON + j]);

        float c[2][4][4];
        #pragma unroll
        for (int rb = 0; rb < 2; ++rb)
            #pragma unroll
            for (int nb = 0; nb < 4; ++nb)
                #pragma unroll
                for (int x = 0; x < 4; ++x) c[rb][nb][x] = 0.f;

        // ---- W-only prefetches first (not gated) — overlap the barrier wait ----
        uint4 Bg0[3], Bg1[3], Bs0[2], Bs1[2];
        #pragma unroll
        for (int p = 0; p < 3; ++p) {
            int kg = WC_KB + warp * TL_KB_W + ((p < TL_KB_W) ? p : TL_KB_W - 1);
            Bg0[p] = __ldg(&gB[((size_t)kg * 32 + lane) * 2 + 0]);
            Bg1[p] = __ldg(&gB[((size_t)kg * 32 + lane) * 2 + 1]);
        }
        {
            uint32_t off = smbase + (uint32_t)((warp * SM_KB_W) * 512 + lane * 16);
            lds128(Bs0[0], off);
            lds128(Bs1[0], off + PLANE_BYTES);
        }

        // ---- wait: all CTAs published generation t ----
        bar_wait(tid, base + 1 + (unsigned)t);

        // ---- A prefetch ring (gated) ----
        uint4 Ar0[3], Ar1[3];
        #pragma unroll
        for (int p = 0; p < 3; ++p) {
            int ka = kb_of(warp, p);
            Ar0[p] = __ldcg(&gA[((size_t)ka * 2 + 0) * 32 + lane]);
            Ar1[p] = __ldcg(&gA[((size_t)ka * 2 + 1) * 32 + lane]);
        }

        #pragma unroll
        for (int i = 0; i < 16; ++i) {
            const int g = i >> 2, r = i & 3;
            uint4 A0 = Ar0[i % 3], A1 = Ar1[i % 3];
            uint4 B0, B1;
            if (r < 3) {
                const int s = g * 3 + r;
                B0 = Bs0[s & 1]; B1 = Bs1[s & 1];
                if (s + 1 < SM_KB_W) {
                    uint32_t off = smbase + (uint32_t)((warp * SM_KB_W + s + 1) * 512 + lane * 16);
                    lds128(Bs0[(s + 1) & 1], off);
                    lds128(Bs1[(s + 1) & 1], off + PLANE_BYTES);
                }
            } else {
                B0 = Bg0[g % 3]; B1 = Bg1[g % 3];
                if (g + 3 < TL_KB_W) {
                    int kg = WC_KB + warp * TL_KB_W + g + 3;
                    Bg0[g % 3] = __ldg(&gB[((size_t)kg * 32 + lane) * 2 + 0]);
                    Bg1[g % 3] = __ldg(&gB[((size_t)kg * 32 + lane) * 2 + 1]);
                }
            }

            mma_16816(c[0][0], A0, B0.x, B0.y);
            mma_16816(c[0][1], A0, B0.z, B0.w);
            mma_16816(c[0][2], A0, B1.x, B1.y);
            mma_16816(c[0][3], A0, B1.z, B1.w);
            mma_16816(c[1][0], A1, B0.x, B0.y);
            mma_16816(c[1][1], A1, B0.z, B0.w);
            mma_16816(c[1][2], A1, B1.x, B1.y);
            mma_16816(c[1][3], A1, B1.z, B1.w);

            if (i + 3 < 16) {
                int nk = kb_of(warp, i + 3);
                Ar0[i % 3] = __ldcg(&gA[((size_t)nk * 2 + 0) * 32 + lane]);
                Ar1[i % 3] = __ldcg(&gA[((size_t)nk * 2 + 1) * 32 + lane]);
            }
        }

        // ---- two-phase cross-warp k-reduction (16 warps -> 8 buffers) ----
        __syncthreads();
        if (warp >= 8) {
            float* myred = red + (warp - 8) * (32 * 32);
            #pragma unroll
            for (int rb = 0; rb < 2; ++rb)
                #pragma unroll
                for (int nb = 0; nb < 4; ++nb)
                    #pragma unroll
                    for (int x = 0; x < 4; ++x) {
                        int m = rb * 16 + (lane >> 2) + ((x >= 2) ? 8 : 0);
                        int n = nb * 8 + (lane & 3) * 2 + (x & 1);
                        myred[m * 32 + n] = c[rb][nb][x];
                    }
        }
        __syncthreads();
        if (warp < 8) {
            float* myred = red + warp * (32 * 32);
            #pragma unroll
            for (int rb = 0; rb < 2; ++rb)
                #pragma unroll
                for (int nb = 0; nb < 4; ++nb)
                    #pragma unroll
                    for (int x = 0; x < 4; ++x) {
                        int m = rb * 16 + (lane >> 2) + ((x >= 2) ? 8 : 0);
                        int n = nb * 8 + (lane & 3) * 2 + (x & 1);
                        myred[m * 32 + n] += c[rb][nb][x];
                    }
        }
        __syncthreads();

        float h[2] = {0.f, 0.f};
        #pragma unroll
        for (int ww = 0; ww < 8; ++ww) {
            float2 p = *(const float2*)&red[ww * (32 * 32) + bb * 32 + jl];
            h[0] += p.x; h[1] += p.y;
        }

        const float fv[2] = {ffv.x, ffv.y};
        #pragma unroll
        for (int x = 0; x < 2; ++x) {
            rc[x] = rc[x] * E_SYN + h[x] * DT_SYN;
            float nl = fmaxf(fv[x] + rc[x], 0.0f);
            rt[x] = rt[x] * E_TAU + nl * DT_TAU;
        }

        // publish next-step A fragments, then arrive (release other CTAs ASAP)
        {
            int kb = j >> 4, kk = j & 15;
            int rb2 = bb >> 4, g = bb & 7;
            int reg   = ((bb >> 3) & 1) | ((kk >> 3) << 1);
            int lane0 = (g << 2) | ((kk & 7) >> 1);
            __half2* basep = (__half2*)g_r16[nxt];
            stcg32(&basep[((size_t)(kb * 2 + rb2) * 32 + lane0) * 4 + reg], h2u(rt[0], rt[1]));
        }
        bar_arrive(tid, base + 2 + (unsigned)t);

        // window accumulation + output (after arrive — off the critical path)
        if (t >= 90) {
            av[0] += rt[0]; av[1] += rt[1];
            if (t >= 100 && ((t - 100) % 10) == 0) {
                const int w = (t - 100) / 10;
                *(float2*)&out[((size_t)bb * 20 + w) * N_NEURON + j] =
                    make_float2(av[0] * 0.1f, av[1] * 0.1f);
                av[0] = av[1] = 0.f;
            }
        }
    }
}

// ---------------- launch ------------------------------------------------------
extern "C" void kernel_launch(void* const* d_in, const int* in_sizes, int n_in,
                              void* d_out, int out_size) {
    const float* W    = (const float*)d_in[0];   // Wab_T [4096,4096] f32
    const float* ff   = (const float*)d_in[1];   // ff_input [32,300,4096] f32
    const float* rec0 = (const float*)d_in[2];   // rec0 [32,4096] f32
    float* out = (float*)d_out;                  // [32,20,4096] f32

    cudaFuncSetAttribute(persist_kernel, cudaFuncAttributeMaxDynamicSharedMemorySize, SMEM_TOTAL);

    convert_w<<<(128 * 256 * 32 + 255) / 256, 256>>>(W);
    persist_kernel<<<NCTA, NTHREAD, SMEM_TOTAL>>>(ff, rec0, out);
}

// round 11
// speedup vs baseline: 1.4820x; 1.1784x over previous
#include <cuda_runtime.h>
#include <cuda_fp16.h>
#include <cstdint>

#define N_NEURON 4096
#define N_BATCH  32
#define N_STEPS  300
#define NCTA     128

// ---------------- device scratch (allocation-free rule: __device__ globals) ----
__device__ __align__(256) __half g_W16[(size_t)N_NEURON * N_NEURON];
__device__ __align__(256) __half g_r16[2][N_BATCH * N_NEURON];
__device__ unsigned g_cnt;
__device__ unsigned g_gen;

// ---------------- W fp32 -> fp16 fragment pack (once per replay) --------------
__global__ void convert_w(const float* __restrict__ W) {
    int idx = blockIdx.x * blockDim.x + threadIdx.x;
    if (idx >= 128 * 256 * 32) return;
    int lane = idx & 31;
    int kb   = (idx >> 5) & 255;
    int jt   = idx >> 13;
    int k0   = kb * 16 + (lane & 3) * 2;
    int g    = lane >> 2;
    __half h[16];
    #pragma unroll
    for (int nb = 0; nb < 4; ++nb) {
        int j = jt * 32 + nb * 8 + g;
        h[nb * 4 + 0] = __float2half(W[(size_t)(k0    ) * N_NEURON + j]);
        h[nb * 4 + 1] = __float2half(W[(size_t)(k0 + 1) * N_NEURON + j]);
        h[nb * 4 + 2] = __float2half(W[(size_t)(k0 + 8) * N_NEURON + j]);
        h[nb * 4 + 3] = __float2half(W[(size_t)(k0 + 9) * N_NEURON + j]);
    }
    uint4* dst = (uint4*)(g_W16 + (size_t)idx * 16);
    dst[0] = ((const uint4*)h)[0];
    dst[1] = ((const uint4*)h)[1];
}

// ---------------- smem layout ---------------------------------------------------
#define WC_KB        192
#define PLANE_BYTES  (WC_KB * 512)            // 98304 per plane
#define RED_OFF      (2 * PLANE_BYTES)        // 196608
#define RED_BYTES    (8 * 32 * 32 * 4)        // 32768
#define SMEM_TOTAL   (RED_OFF + RED_BYTES)    // 229376 = 224 KB

#define ADEPTH       6                        // A prefetch ring depth (was 3)

__device__ __forceinline__ unsigned ld_acq(unsigned* p) {
    unsigned v;
    asm volatile("ld.acquire.gpu.global.u32 %0, [%1];" : "=r"(v) : "l"(p) : "memory");
    return v;
}

__device__ __forceinline__ void grid_barrier(int tid, unsigned target) {
    __syncthreads();
    if (tid == 0) {
        __threadfence();
        unsigned arr = atomicAdd(&g_cnt, 1);
        if (arr == NCTA - 1) {
            atomicExch(&g_cnt, 0);
            __threadfence();
            atomicExch(&g_gen, target);
        } else {
            while ((int)(ld_acq(&g_gen) - target) < 0) {}
        }
    }
    __syncthreads();
}

__device__ __forceinline__ void lds128(uint4& d, uint32_t addr) {
    asm volatile("ld.shared.v4.u32 {%0,%1,%2,%3}, [%4];"
        : "=r"(d.x), "=r"(d.y), "=r"(d.z), "=r"(d.w) : "r"(addr));
}
__device__ __forceinline__ void stcg32(void* p, uint32_t v) {
    asm volatile("st.global.cg.u32 [%0], %1;" :: "l"(p), "r"(v) : "memory");
}
__device__ __forceinline__ uint32_t h2u(float a, float b) {
    __half2 h = __floats2half2_rn(a, b);
    return *(uint32_t*)&h;
}
__device__ __forceinline__ void mma_16816(float c[4], const uint4& a, uint32_t b0, uint32_t b1) {
    asm volatile("mma.sync.aligned.m16n8k16.row.col.f32.f16.f16.f32 "
        "{%0,%1,%2,%3}, {%4,%5,%6,%7}, {%8,%9}, {%0,%1,%2,%3};\n"
        : "+f"(c[0]), "+f"(c[1]), "+f"(c[2]), "+f"(c[3])
        : "r"(a.x), "r"(a.y), "r"(a.z), "r"(a.w), "r"(b0), "r"(b1));
}
// kb index used by warp at mainloop iteration i (3 smem + 1 tail per 4 iters)
__device__ __forceinline__ int kb_of(int warp, int i) {
    int g = i >> 2, r = i & 3;
    return (r < 3) ? (warp * 24 + g * 3 + r) : (WC_KB + warp * 8 + g);
}

// ---------------- persistent fused simulation kernel ---------------------------
__global__ void __launch_bounds__(256, 1) persist_kernel(
    const float* __restrict__ ff, const float* __restrict__ rec0,
    float* __restrict__ out)
{
    extern __shared__ __align__(16) char sm[];
    float* red = (float*)(sm + RED_OFF);

    const int tid  = threadIdx.x;
    const int warp = tid >> 5;
    const int lane = tid & 31;
    const int jt   = blockIdx.x;
    const int j0   = jt * 32;

    uint32_t smbase;
    asm("{ .reg .u64 t0; cvta.to.shared.u64 t0, %1; cvt.u32.u64 %0, t0; }"
        : "=r"(smbase) : "l"(sm));

    const uint4* __restrict__ gB = (const uint4*)g_W16 + (size_t)jt * 256 * 64;

    const int bb = tid >> 3;
    const int jl = (tid & 7) * 4;
    const int j  = j0 + jl;

    unsigned tgt = ld_acq(&g_gen);   // relative base: replay-safe

    // ---- prologue: cache first 192 kb-entries of W stripe into two smem planes
    {
        const char* src = (const char*)gB;
        for (int s = tid; s < WC_KB * 32; s += 256) {
            uint32_t d0 = smbase + s * 16;
            uint32_t d1 = smbase + PLANE_BYTES + s * 16;
            const char* g0 = src + (size_t)s * 32;
            asm volatile("cp.async.cg.shared.global [%0], [%1], 16;" :: "r"(d0), "l"(g0));
            asm volatile("cp.async.cg.shared.global [%0], [%1], 16;" :: "r"(d1), "l"(g0 + 16));
        }
        asm volatile("cp.async.commit_group;");
        asm volatile("cp.async.wait_group 0;");
    }

    // ---- state init in registers ----
    float rc[4], rt[4], av[4];
    {
        const size_t idx = (size_t)bb * N_NEURON + j;
        float4 r0 = *(const float4*)&rec0[idx];
        float4 f0 = __ldg((const float4*)&ff[((size_t)bb * N_STEPS) * N_NEURON + j]);
        rc[0] = r0.x; rc[1] = r0.y; rc[2] = r0.z; rc[3] = r0.w;
        rt[0] = fmaxf(f0.x + r0.x, 0.f); rt[1] = fmaxf(f0.y + r0.y, 0.f);
        rt[2] = fmaxf(f0.z + r0.z, 0.f); rt[3] = fmaxf(f0.w + r0.w, 0.f);
        av[0] = av[1] = av[2] = av[3] = 0.f;
        int kb = j >> 4, kk = j & 15;
        int rb2 = bb >> 4, g = bb & 7;
        int reg   = ((bb >> 3) & 1) | ((kk >> 3) << 1);
        int lane0 = (g << 2) | ((kk & 7) >> 1);
        __half2* basep = (__half2*)g_r16[0];
        stcg32(&basep[((size_t)(kb * 2 + rb2) * 32 + lane0    ) * 4 + reg], h2u(rt[0], rt[1]));
        stcg32(&basep[((size_t)(kb * 2 + rb2) * 32 + lane0 + 1) * 4 + reg], h2u(rt[2], rt[3]));
    }
    grid_barrier(tid, ++tgt);

    const float E_SYN  = 0.95122942450071403f;
    const float DT_SYN = 0.05f;
    const float E_TAU  = 0.90483741803595957f;
    const float DT_TAU = 0.1f;

    for (int t = 0; t < N_STEPS; ++t) {
        const int cur = t & 1, nxt = cur ^ 1;
        const uint4* __restrict__ gA = (const uint4*)g_r16[cur];

        const float4 ffv = __ldg((const float4*)&ff[((size_t)bb * N_STEPS + t) * N_NEURON + j]);

        float c[2][4][4];
        #pragma unroll
        for (int rb = 0; rb < 2; ++rb)
            #pragma unroll
            for (int nb = 0; nb < 4; ++nb)
                #pragma unroll
                for (int i = 0; i < 4; ++i) c[rb][nb][i] = 0.f;

        // ---- prefetch rings: deep A ring (6), B tail ring (2), B smem dbl-buf --
        uint4 Ar0[ADEPTH], Ar1[ADEPTH], Bg0[2], Bg1[2], Bs0[2], Bs1[2];
        #pragma unroll
        for (int p = 0; p < ADEPTH; ++p) {
            int ka = kb_of(warp, p);
            Ar0[p] = __ldcg(&gA[((size_t)ka * 2 + 0) * 32 + lane]);
            Ar1[p] = __ldcg(&gA[((size_t)ka * 2 + 1) * 32 + lane]);
        }
        #pragma unroll
        for (int p = 0; p < 2; ++p) {
            int kg = WC_KB + warp * 8 + p;
            Bg0[p] = __ldg(&gB[((size_t)kg * 32 + lane) * 2 + 0]);
            Bg1[p] = __ldg(&gB[((size_t)kg * 32 + lane) * 2 + 1]);
        }
        {
            uint32_t off = smbase + (uint32_t)((warp * 24) * 512 + lane * 16);
            lds128(Bs0[0], off);
            lds128(Bs1[0], off + PLANE_BYTES);
        }

        #pragma unroll
        for (int i = 0; i < 32; ++i) {
            const int g = i >> 2, r = i & 3;
            uint4 A0 = Ar0[i % ADEPTH], A1 = Ar1[i % ADEPTH];
            uint4 B0, B1;
            if (r < 3) {
                const int s = g * 3 + r;
                B0 = Bs0[s & 1]; B1 = Bs1[s & 1];
                if (s + 1 < 24) {
                    uint32_t off = smbase + (uint32_t)((warp * 24 + s + 1) * 512 + lane * 16);
                    lds128(Bs0[(s + 1) & 1], off);
                    lds128(Bs1[(s + 1) & 1], off + PLANE_BYTES);
                }
            } else {
                B0 = Bg0[g & 1]; B1 = Bg1[g & 1];
                if (g + 2 < 8) {
                    int kg = WC_KB + warp * 8 + g + 2;
                    Bg0[g & 1] = __ldg(&gB[((size_t)kg * 32 + lane) * 2 + 0]);
                    Bg1[g & 1] = __ldg(&gB[((size_t)kg * 32 + lane) * 2 + 1]);
                }
            }

            mma_16816(c[0][0], A0, B0.x, B0.y);
            mma_16816(c[0][1], A0, B0.z, B0.w);
            mma_16816(c[0][2], A0, B1.x, B1.y);
            mma_16816(c[0][3], A0, B1.z, B1.w);
            mma_16816(c[1][0], A1, B0.x, B0.y);
            mma_16816(c[1][1], A1, B0.z, B0.w);
            mma_16816(c[1][2], A1, B1.x, B1.y);
            mma_16816(c[1][3], A1, B1.z, B1.w);

            if (i + ADEPTH < 32) {
                int nk = kb_of(warp, i + ADEPTH);
                Ar0[i % ADEPTH] = __ldcg(&gA[((size_t)nk * 2 + 0) * 32 + lane]);
                Ar1[i % ADEPTH] = __ldcg(&gA[((size_t)nk * 2 + 1) * 32 + lane]);
            }
        }

        // ---- cross-warp k-reduction through smem (single phase, as in R6) ----
        float* myred = red + warp * (32 * 32);
        #pragma unroll
        for (int rb = 0; rb < 2; ++rb)
            #pragma unroll
            for (int nb = 0; nb < 4; ++nb)
                #pragma unroll
                for (int i = 0; i < 4; ++i) {
                    int m = rb * 16 + (lane >> 2) + ((i >= 2) ? 8 : 0);
                    int n = nb * 8 + (lane & 3) * 2 + (i & 1);
                    myred[m * 32 + n] = c[rb][nb][i];
                }
        __syncthreads();

        float h[4] = {0.f, 0.f, 0.f, 0.f};
        #pragma unroll
        for (int ww = 0; ww < 8; ++ww) {
            float4 p = *(const float4*)&red[ww * (32 * 32) + bb * 32 + jl];
            h[0] += p.x; h[1] += p.y; h[2] += p.z; h[3] += p.w;
        }

        const float fv[4] = {ffv.x, ffv.y, ffv.z, ffv.w};
        #pragma unroll
        for (int x = 0; x < 4; ++x) {
            rc[x] = rc[x] * E_SYN + h[x] * DT_SYN;
            float nl = fmaxf(fv[x] + rc[x], 0.0f);
            rt[x] = rt[x] * E_TAU + nl * DT_TAU;
        }

        {
            int kb = j >> 4, kk = j & 15;
            int rb2 = bb >> 4, g = bb & 7;
            int reg   = ((bb >> 3) & 1) | ((kk >> 3) << 1);
            int lane0 = (g << 2) | ((kk & 7) >> 1);
            __half2* basep = (__half2*)g_r16[nxt];
            stcg32(&basep[((size_t)(kb * 2 + rb2) * 32 + lane0    ) * 4 + reg], h2u(rt[0], rt[1]));
            stcg32(&basep[((size_t)(kb * 2 + rb2) * 32 + lane0 + 1) * 4 + reg], h2u(rt[2], rt[3]));
        }

        if (t >= 90) {
            av[0] += rt[0]; av[1] += rt[1]; av[2] += rt[2]; av[3] += rt[3];
            if (t >= 100 && ((t - 100) % 10) == 0) {
                const int w = (t - 100) / 10;
                *(float4*)&out[((size_t)bb * 20 + w) * N_NEURON + j] =
                    make_float4(av[0] * 0.1f, av[1] * 0.1f, av[2] * 0.1f, av[3] * 0.1f);
                av[0] = av[1] = av[2] = av[3] = 0.f;
            }
        }

        if (t < N_STEPS - 1) grid_barrier(tid, ++tgt);
    }
}

// ---------------- launch ------------------------------------------------------
extern "C" void kernel_launch(void* const* d_in, const int* in_sizes, int n_in,
                              void* d_out, int out_size) {
    const float* W    = (const float*)d_in[0];   // Wab_T [4096,4096] f32
    const float* ff   = (const float*)d_in[1];   // ff_input [32,300,4096] f32
    const float* rec0 = (const float*)d_in[2];   // rec0 [32,4096] f32
    float* out = (float*)d_out;                  // [32,20,4096] f32

    cudaFuncSetAttribute(persist_kernel, cudaFuncAttributeMaxDynamicSharedMemorySize, SMEM_TOTAL);

    convert_w<<<(128 * 256 * 32 + 255) / 256, 256>>>(W);
    persist_kernel<<<NCTA, 256, SMEM_TOTAL>>>(ff, rec0, out);
}